// round 4
// baseline (speedup 1.0000x reference)
#include <cuda_runtime.h>
#include <math.h>

#define DM    1024
#define NH    16
#define HD    64
#define BATCH 2
#define SEQ   2048
#define MROWS (BATCH*SEQ)      // 4096

// Scratch (device globals — no allocation allowed)
__device__ float g_q [MROWS*DM];
__device__ float g_k [MROWS*DM];   // pre-scaled by 1/sqrt(HD)
__device__ float g_v [MROWS*DM];
__device__ float g_c1[MROWS*DM];
__device__ float g_c2[MROWS*DM];

__device__ __forceinline__ unsigned f2tf(float f) {
    unsigned u;
    asm("cvt.rna.tf32.f32 %0, %1;" : "=r"(u) : "f"(f));
    return u;
}

__device__ __forceinline__ void mma8(float* d, const unsigned* a,
                                     unsigned b0, unsigned b1) {
    asm volatile(
        "mma.sync.aligned.m16n8k8.row.col.f32.tf32.tf32.f32 "
        "{%0,%1,%2,%3}, {%4,%5,%6,%7}, {%8,%9}, {%0,%1,%2,%3};"
        : "+f"(d[0]), "+f"(d[1]), "+f"(d[2]), "+f"(d[3])
        : "r"(a[0]), "r"(a[1]), "r"(a[2]), "r"(a[3]), "r"(b0), "r"(b1));
}

// ---------------------------------------------------------------------------
// TF32 tensor-core GEMM: C[M,N] = A[M,K] @ Bw[N,K]^T + bias[N]
// MODE 0: plain write; MODE 1: qkv scatter (k scaled by 0.125)
// CTA tile 128x128, 256 threads (8 warps 4x2), warp tile 32x64, kc=16.
// ---------------------------------------------------------------------------
template<int MODE>
__global__ __launch_bounds__(256)
void gemm_tc(const float* __restrict__ A, const float* __restrict__ Bw,
             const float* __restrict__ bias, float* __restrict__ C,
             int M, int N, int K,
             float* __restrict__ qo, float* __restrict__ ko,
             float* __restrict__ vo)
{
    __shared__ unsigned As[128][20];
    __shared__ unsigned Bs[128][20];

    const int tid = threadIdx.x;
    const int wid = tid >> 5, lane = tid & 31;
    const int lg = lane >> 2, la3 = lane & 3;
    const int wm = wid & 3, wn = wid >> 2;          // warp grid 4x2
    const int bm = blockIdx.y * 128, bn = blockIdx.x * 128;

    float acc[2][8][4];
    #pragma unroll
    for (int mt = 0; mt < 2; mt++)
        #pragma unroll
        for (int nt = 0; nt < 8; nt++)
            #pragma unroll
            for (int i = 0; i < 4; i++) acc[mt][nt][i] = 0.f;

    const int lrow = tid >> 2, lcol = (tid & 3) * 4;   // 64 rows x 16 cols
    const float* Ap = A  + (size_t)(bm + lrow) * K + lcol;
    const float* Bp = Bw + (size_t)(bn + lrow) * K + lcol;

    // prefetch chunk 0
    float4 a0 = *(const float4*)(Ap);
    float4 a1 = *(const float4*)(Ap + (size_t)64 * K);
    float4 b0 = *(const float4*)(Bp);
    float4 b1 = *(const float4*)(Bp + (size_t)64 * K);

    for (int k0 = 0; k0 < K; k0 += 16) {
        __syncthreads();
        *(uint4*)&As[lrow   ][lcol] = make_uint4(f2tf(a0.x), f2tf(a0.y), f2tf(a0.z), f2tf(a0.w));
        *(uint4*)&As[lrow+64][lcol] = make_uint4(f2tf(a1.x), f2tf(a1.y), f2tf(a1.z), f2tf(a1.w));
        *(uint4*)&Bs[lrow   ][lcol] = make_uint4(f2tf(b0.x), f2tf(b0.y), f2tf(b0.z), f2tf(b0.w));
        *(uint4*)&Bs[lrow+64][lcol] = make_uint4(f2tf(b1.x), f2tf(b1.y), f2tf(b1.z), f2tf(b1.w));
        if (k0 + 16 < K) {
            a0 = *(const float4*)(Ap + k0 + 16);
            a1 = *(const float4*)(Ap + (size_t)64 * K + k0 + 16);
            b0 = *(const float4*)(Bp + k0 + 16);
            b1 = *(const float4*)(Bp + (size_t)64 * K + k0 + 16);
        }
        __syncthreads();

        #pragma unroll
        for (int ks = 0; ks < 2; ks++) {
            unsigned af[2][4], bf[8][2];
            #pragma unroll
            for (int mt = 0; mt < 2; mt++) {
                const int r = wm * 32 + mt * 16 + lg;
                af[mt][0] = As[r    ][ks * 8 + la3];
                af[mt][1] = As[r + 8][ks * 8 + la3];
                af[mt][2] = As[r    ][ks * 8 + la3 + 4];
                af[mt][3] = As[r + 8][ks * 8 + la3 + 4];
            }
            #pragma unroll
            for (int nt = 0; nt < 8; nt++) {
                const int n = wn * 64 + nt * 8 + lg;
                bf[nt][0] = Bs[n][ks * 8 + la3];
                bf[nt][1] = Bs[n][ks * 8 + la3 + 4];
            }
            #pragma unroll
            for (int mt = 0; mt < 2; mt++)
                #pragma unroll
                for (int nt = 0; nt < 8; nt++)
                    mma8(acc[mt][nt], af[mt], bf[nt][0], bf[nt][1]);
        }
    }

    #pragma unroll
    for (int mt = 0; mt < 2; mt++)
        #pragma unroll
        for (int nt = 0; nt < 8; nt++)
            #pragma unroll
            for (int i = 0; i < 4; i++) {
                const int row = bm + wm * 32 + mt * 16 + lg + (i >> 1) * 8;
                const int col = bn + wn * 64 + nt * 8 + 2 * la3 + (i & 1);
                float val = acc[mt][nt][i] + bias[col];
                if (MODE == 0) {
                    C[(size_t)row * N + col] = val;
                } else {
                    const int g   = col >> 10;
                    const int rem = col & 1023;
                    if (g == 1) val *= 0.125f;
                    float* dst = (g == 0) ? qo : (g == 1) ? ko : vo;
                    dst[(size_t)row * DM + rem] = val;
                }
            }
}

// ---------------------------------------------------------------------------
// TF32 tensor-core causal flash attention.
// CTA: 128 threads (4 warps), 64-row Q tile, head dim 64.
// Q fragments register-resident (direct gmem load, once). smem = Ks+Vs+Ps
// (52KB) -> 4 CTAs/SM; regs capped at 128 via launch_bounds(128,4).
// ---------------------------------------------------------------------------
#define KP 68   // pad: bank = 4*lg+la3 -> conflict-free frag loads
#define VP 72   // pad: bank = 8*la3+lg -> conflict-free PV-B frag loads
#define ATTN_SMEM ((64*KP + 64*VP + 64*KP) * 4)  // Ks,Vs,Ps = 52KB

__global__ __launch_bounds__(128, 4)
void attn_tc(const float* __restrict__ Qb, const float* __restrict__ Kb,
             const float* __restrict__ Vb, float* __restrict__ Ob)
{
    extern __shared__ unsigned sm[];
    unsigned (*Ks)[KP] = (unsigned(*)[KP])sm;                 // [64][68]
    unsigned (*Vs)[VP] = (unsigned(*)[VP])(sm + 64*KP);       // [64][72]
    unsigned (*Ps)[KP] = (unsigned(*)[KP])(sm + 64*KP + 64*VP); // [64][68]

    const int qt = (int)gridDim.x - 1 - (int)blockIdx.x;      // long rows first
    const int h = blockIdx.y, b = blockIdx.z;
    const int tid = threadIdx.x, wid = tid >> 5, lane = tid & 31;
    const int lg = lane >> 2, la3 = lane & 3;
    const int wb = wid * 16;
    const float NEG_INF = __int_as_float(0xff800000);

    const size_t base = (size_t)b * SEQ * DM + (size_t)h * HD;
    const int lr = tid >> 4, lc = (tid & 15) * 4;   // 8 rows x 64 cols / iter

    // ---- Q fragments: direct gmem load, register-resident for whole CTA ----
    unsigned Qf[8][4];
    {
        const float* q0 = Qb + base + (size_t)(qt * 64 + wb + lg) * DM;
        const float* q1 = q0 + (size_t)8 * DM;
        #pragma unroll
        for (int k8 = 0; k8 < 8; k8++) {
            Qf[k8][0] = f2tf(q0[k8 * 8 + la3]);
            Qf[k8][1] = f2tf(q1[k8 * 8 + la3]);
            Qf[k8][2] = f2tf(q0[k8 * 8 + la3 + 4]);
            Qf[k8][3] = f2tf(q1[k8 * 8 + la3 + 4]);
        }
    }

    float m0 = NEG_INF, m1 = NEG_INF, l0 = 0.f, l1 = 0.f;
    float O[8][4];
    #pragma unroll
    for (int nt = 0; nt < 8; nt++)
        #pragma unroll
        for (int i = 0; i < 4; i++) O[nt][i] = 0.f;

    for (int kt = 0; kt <= qt; kt++) {
        if (kt) __syncthreads();       // prev tile's smem reads done

        // ---- stage K and V tiles ----
        const float* Kg = Kb + base + (size_t)(kt * 64) * DM;
        const float* Vg = Vb + base + (size_t)(kt * 64) * DM;
        #pragma unroll
        for (int i = 0; i < 8; i++) {
            const int r = lr + i * 8;
            float4 kv = *(const float4*)(Kg + (size_t)r * DM + lc);
            *(uint4*)&Ks[r][lc] = make_uint4(f2tf(kv.x), f2tf(kv.y), f2tf(kv.z), f2tf(kv.w));
            float4 vv = *(const float4*)(Vg + (size_t)r * DM + lc);
            *(uint4*)&Vs[r][lc] = make_uint4(f2tf(vv.x), f2tf(vv.y), f2tf(vv.z), f2tf(vv.w));
        }
        __syncthreads();               // Ks/Vs ready

        // ---- S = Q @ K^T (16x64 per warp) ----
        float S[8][4];
        #pragma unroll
        for (int nt = 0; nt < 8; nt++)
            #pragma unroll
            for (int i = 0; i < 4; i++) S[nt][i] = 0.f;

        #pragma unroll
        for (int k8 = 0; k8 < 8; k8++)
            #pragma unroll
            for (int nt = 0; nt < 8; nt++) {
                unsigned b0 = Ks[nt * 8 + lg][k8 * 8 + la3];
                unsigned b1 = Ks[nt * 8 + lg][k8 * 8 + la3 + 4];
                mma8(S[nt], Qf[k8], b0, b1);
            }

        // ---- Causal mask (diagonal tile only) ----
        if (kt == qt) {
            #pragma unroll
            for (int nt = 0; nt < 8; nt++) {
                const int c0 = nt * 8 + 2 * la3;
                const int r0 = wb + lg, r1 = r0 + 8;
                if (c0     > r0) S[nt][0] = NEG_INF;
                if (c0 + 1 > r0) S[nt][1] = NEG_INF;
                if (c0     > r1) S[nt][2] = NEG_INF;
                if (c0 + 1 > r1) S[nt][3] = NEG_INF;
            }
        }

        // ---- Online softmax (rows r0, r1; 4-lane quads) ----
        float mx0 = NEG_INF, mx1 = NEG_INF;
        #pragma unroll
        for (int nt = 0; nt < 8; nt++) {
            mx0 = fmaxf(mx0, fmaxf(S[nt][0], S[nt][1]));
            mx1 = fmaxf(mx1, fmaxf(S[nt][2], S[nt][3]));
        }
        mx0 = fmaxf(mx0, __shfl_xor_sync(0xffffffffu, mx0, 1));
        mx0 = fmaxf(mx0, __shfl_xor_sync(0xffffffffu, mx0, 2));
        mx1 = fmaxf(mx1, __shfl_xor_sync(0xffffffffu, mx1, 1));
        mx1 = fmaxf(mx1, __shfl_xor_sync(0xffffffffu, mx1, 2));
        const float mn0 = fmaxf(m0, mx0), mn1 = fmaxf(m1, mx1);
        const float al0 = __expf(m0 - mn0), al1 = __expf(m1 - mn1);
        float rs0 = 0.f, rs1 = 0.f;
        #pragma unroll
        for (int nt = 0; nt < 8; nt++) {
            S[nt][0] = __expf(S[nt][0] - mn0);
            S[nt][1] = __expf(S[nt][1] - mn0);
            S[nt][2] = __expf(S[nt][2] - mn1);
            S[nt][3] = __expf(S[nt][3] - mn1);
            rs0 += S[nt][0] + S[nt][1];
            rs1 += S[nt][2] + S[nt][3];
        }
        rs0 += __shfl_xor_sync(0xffffffffu, rs0, 1);
        rs0 += __shfl_xor_sync(0xffffffffu, rs0, 2);
        rs1 += __shfl_xor_sync(0xffffffffu, rs1, 1);
        rs1 += __shfl_xor_sync(0xffffffffu, rs1, 2);
        l0 = l0 * al0 + rs0;  m0 = mn0;
        l1 = l1 * al1 + rs1;  m1 = mn1;
        #pragma unroll
        for (int nt = 0; nt < 8; nt++) {
            O[nt][0] *= al0;  O[nt][1] *= al0;
            O[nt][2] *= al1;  O[nt][3] *= al1;
        }

        // ---- P -> per-warp-private smem rows (syncwarp sufficient) ----
        #pragma unroll
        for (int nt = 0; nt < 8; nt++) {
            *(uint2*)&Ps[wb + lg    ][nt * 8 + 2 * la3] =
                make_uint2(f2tf(S[nt][0]), f2tf(S[nt][1]));
            *(uint2*)&Ps[wb + lg + 8][nt * 8 + 2 * la3] =
                make_uint2(f2tf(S[nt][2]), f2tf(S[nt][3]));
        }
        __syncwarp();

        // ---- O += P @ V ----
        #pragma unroll
        for (int k8 = 0; k8 < 8; k8++) {
            unsigned pf[4];
            pf[0] = Ps[wb + lg    ][k8 * 8 + la3];
            pf[1] = Ps[wb + lg + 8][k8 * 8 + la3];
            pf[2] = Ps[wb + lg    ][k8 * 8 + la3 + 4];
            pf[3] = Ps[wb + lg + 8][k8 * 8 + la3 + 4];
            #pragma unroll
            for (int nt = 0; nt < 8; nt++) {
                unsigned b0 = Vs[k8 * 8 + la3    ][nt * 8 + lg];
                unsigned b1 = Vs[k8 * 8 + la3 + 4][nt * 8 + lg];
                mma8(O[nt], pf, b0, b1);
            }
        }
    }

    // ---- Epilogue ----
    float* Og = Ob + base + (size_t)(qt * 64) * DM;
    const float il0 = 1.0f / l0, il1 = 1.0f / l1;
    #pragma unroll
    for (int nt = 0; nt < 8; nt++) {
        const int col = nt * 8 + 2 * la3;
        *(float2*)(Og + (size_t)(wb + lg    ) * DM + col) =
            make_float2(O[nt][0] * il0, O[nt][1] * il0);
        *(float2*)(Og + (size_t)(wb + lg + 8) * DM + col) =
            make_float2(O[nt][2] * il1, O[nt][3] * il1);
    }
}

// ---------------------------------------------------------------------------
extern "C" void kernel_launch(void* const* d_in, const int* in_sizes, int n_in,
                              void* d_out, int out_size)
{
    const float* x  = (const float*)d_in[0];
    const float* Ww = (const float*)d_in[1];
    const float* Wb = (const float*)d_in[2];
    const float* Ow = (const float*)d_in[3];
    const float* Ob = (const float*)d_in[4];
    float* out = (float*)d_out;

    float *q, *k, *v, *c1, *c2;
    cudaGetSymbolAddress((void**)&q,  g_q);
    cudaGetSymbolAddress((void**)&k,  g_k);
    cudaGetSymbolAddress((void**)&v,  g_v);
    cudaGetSymbolAddress((void**)&c1, g_c1);
    cudaGetSymbolAddress((void**)&c2, g_c2);

    cudaFuncSetAttribute(attn_tc,
                         cudaFuncAttributeMaxDynamicSharedMemorySize, ATTN_SMEM);

    // 1) QKV projection + bias, scatter into q/k/v (k pre-scaled by 1/8)
    dim3 g1(3 * DM / 128, MROWS / 128);
    gemm_tc<1><<<g1, 256>>>(x, Ww, Wb, nullptr, MROWS, 3 * DM, DM, q, k, v);

    // 2-4) repeated causal attention
    dim3 ga(SEQ / 64, NH, BATCH);
    attn_tc<<<ga, 128, ATTN_SMEM>>>(q,  k, v, c1);
    attn_tc<<<ga, 128, ATTN_SMEM>>>(c1, k, v, c2);
    attn_tc<<<ga, 128, ATTN_SMEM>>>(c2, k, v, c1);

    // 5) output projection + bias
    dim3 g2(DM / 128, MROWS / 128);
    gemm_tc<0><<<g2, 256>>>(c1, Ow, Ob, out, MROWS, DM, DM,
                            nullptr, nullptr, nullptr);
}

// round 5
// speedup vs baseline: 1.0168x; 1.0168x over previous
#include <cuda_runtime.h>
#include <math.h>

#define DM    1024
#define NH    16
#define HD    64
#define BATCH 2
#define SEQ   2048
#define MROWS (BATCH*SEQ)      // 4096

// Scratch (device globals — no allocation allowed)
__device__ float g_q [MROWS*DM];
__device__ float g_k [MROWS*DM];   // pre-scaled by 1/sqrt(HD)
__device__ float g_v [MROWS*DM];
__device__ float g_c1[MROWS*DM];
__device__ float g_c2[MROWS*DM];

__device__ __forceinline__ unsigned f2tf(float f) {
    unsigned u;
    asm("cvt.rna.tf32.f32 %0, %1;" : "=r"(u) : "f"(f));
    return u;
}

__device__ __forceinline__ void mma8(float* d, const unsigned* a,
                                     unsigned b0, unsigned b1) {
    asm volatile(
        "mma.sync.aligned.m16n8k8.row.col.f32.tf32.tf32.f32 "
        "{%0,%1,%2,%3}, {%4,%5,%6,%7}, {%8,%9}, {%0,%1,%2,%3};"
        : "+f"(d[0]), "+f"(d[1]), "+f"(d[2]), "+f"(d[3])
        : "r"(a[0]), "r"(a[1]), "r"(a[2]), "r"(a[3]), "r"(b0), "r"(b1));
}

// ---------------------------------------------------------------------------
// TF32 tensor-core GEMM: C[M,N] = A[M,K] @ Bw[N,K]^T + bias[N]
// MODE 0: plain write; MODE 1: qkv scatter (k scaled by 0.125)
// CTA tile 128x128, 256 threads (8 warps 4x2), warp tile 32x64, kc=16.
// ---------------------------------------------------------------------------
template<int MODE>
__global__ __launch_bounds__(256)
void gemm_tc(const float* __restrict__ A, const float* __restrict__ Bw,
             const float* __restrict__ bias, float* __restrict__ C,
             int M, int N, int K,
             float* __restrict__ qo, float* __restrict__ ko,
             float* __restrict__ vo)
{
    __shared__ unsigned As[128][20];
    __shared__ unsigned Bs[128][20];

    const int tid = threadIdx.x;
    const int wid = tid >> 5, lane = tid & 31;
    const int lg = lane >> 2, la3 = lane & 3;
    const int wm = wid & 3, wn = wid >> 2;          // warp grid 4x2
    const int bm = blockIdx.y * 128, bn = blockIdx.x * 128;

    float acc[2][8][4];
    #pragma unroll
    for (int mt = 0; mt < 2; mt++)
        #pragma unroll
        for (int nt = 0; nt < 8; nt++)
            #pragma unroll
            for (int i = 0; i < 4; i++) acc[mt][nt][i] = 0.f;

    const int lrow = tid >> 2, lcol = (tid & 3) * 4;   // 64 rows x 16 cols
    const float* Ap = A  + (size_t)(bm + lrow) * K + lcol;
    const float* Bp = Bw + (size_t)(bn + lrow) * K + lcol;

    float4 a0 = *(const float4*)(Ap);
    float4 a1 = *(const float4*)(Ap + (size_t)64 * K);
    float4 b0 = *(const float4*)(Bp);
    float4 b1 = *(const float4*)(Bp + (size_t)64 * K);

    for (int k0 = 0; k0 < K; k0 += 16) {
        __syncthreads();
        *(uint4*)&As[lrow   ][lcol] = make_uint4(f2tf(a0.x), f2tf(a0.y), f2tf(a0.z), f2tf(a0.w));
        *(uint4*)&As[lrow+64][lcol] = make_uint4(f2tf(a1.x), f2tf(a1.y), f2tf(a1.z), f2tf(a1.w));
        *(uint4*)&Bs[lrow   ][lcol] = make_uint4(f2tf(b0.x), f2tf(b0.y), f2tf(b0.z), f2tf(b0.w));
        *(uint4*)&Bs[lrow+64][lcol] = make_uint4(f2tf(b1.x), f2tf(b1.y), f2tf(b1.z), f2tf(b1.w));
        if (k0 + 16 < K) {
            a0 = *(const float4*)(Ap + k0 + 16);
            a1 = *(const float4*)(Ap + (size_t)64 * K + k0 + 16);
            b0 = *(const float4*)(Bp + k0 + 16);
            b1 = *(const float4*)(Bp + (size_t)64 * K + k0 + 16);
        }
        __syncthreads();

        #pragma unroll
        for (int ks = 0; ks < 2; ks++) {
            unsigned af[2][4], bf[8][2];
            #pragma unroll
            for (int mt = 0; mt < 2; mt++) {
                const int r = wm * 32 + mt * 16 + lg;
                af[mt][0] = As[r    ][ks * 8 + la3];
                af[mt][1] = As[r + 8][ks * 8 + la3];
                af[mt][2] = As[r    ][ks * 8 + la3 + 4];
                af[mt][3] = As[r + 8][ks * 8 + la3 + 4];
            }
            #pragma unroll
            for (int nt = 0; nt < 8; nt++) {
                const int n = wn * 64 + nt * 8 + lg;
                bf[nt][0] = Bs[n][ks * 8 + la3];
                bf[nt][1] = Bs[n][ks * 8 + la3 + 4];
            }
            #pragma unroll
            for (int mt = 0; mt < 2; mt++)
                #pragma unroll
                for (int nt = 0; nt < 8; nt++)
                    mma8(acc[mt][nt], af[mt], bf[nt][0], bf[nt][1]);
        }
    }

    #pragma unroll
    for (int mt = 0; mt < 2; mt++)
        #pragma unroll
        for (int nt = 0; nt < 8; nt++)
            #pragma unroll
            for (int i = 0; i < 4; i++) {
                const int row = bm + wm * 32 + mt * 16 + lg + (i >> 1) * 8;
                const int col = bn + wn * 64 + nt * 8 + 2 * la3 + (i & 1);
                float val = acc[mt][nt][i] + bias[col];
                if (MODE == 0) {
                    C[(size_t)row * N + col] = val;
                } else {
                    const int g   = col >> 10;
                    const int rem = col & 1023;
                    if (g == 1) val *= 0.125f;
                    float* dst = (g == 0) ? qo : (g == 1) ? ko : vo;
                    dst[(size_t)row * DM + rem] = val;
                }
            }
}

// ---------------------------------------------------------------------------
// TF32 tensor-core causal flash attention.
// CTA: 128 threads (4 warps), Q tile 128 rows, warp = 32 rows (2 m-tiles),
// kv tile 64. Every K/V B-fragment LDS feeds 2 MMAs; K/V staged once per
// 128 q-rows. smem 103KB -> 2 CTAs/SM.
// ---------------------------------------------------------------------------
#define KP 68   // pad: bank = 4*lg+la3 -> conflict-free frag loads
#define VP 72   // pad: bank = 8*la3+lg -> conflict-free PV-B frag loads
#define ATTN_SMEM ((128*KP + 64*KP + 64*VP + 128*KP) * 4)   // Qs,Ks,Vs,Ps

__global__ __launch_bounds__(128, 2)
void attn_tc(const float* __restrict__ Qb, const float* __restrict__ Kb,
             const float* __restrict__ Vb, float* __restrict__ Ob)
{
    extern __shared__ unsigned sm[];
    unsigned (*Qs)[KP] = (unsigned(*)[KP])sm;                         // [128][68]
    unsigned (*Ks)[KP] = (unsigned(*)[KP])(sm + 128*KP);              // [64][68]
    unsigned (*Vs)[VP] = (unsigned(*)[VP])(sm + 128*KP + 64*KP);      // [64][72]
    unsigned (*Ps)[KP] = (unsigned(*)[KP])(sm + 128*KP + 64*KP + 64*VP); // [128][68]

    const int qt = (int)gridDim.x - 1 - (int)blockIdx.x;   // long rows first
    const int h = blockIdx.y, b = blockIdx.z;
    const int tid = threadIdx.x, wid = tid >> 5, lane = tid & 31;
    const int lg = lane >> 2, la3 = lane & 3;
    const int wb = wid * 32;                               // warp's 32-row band
    const float NEG_INF = __int_as_float(0xff800000);

    const size_t base = (size_t)b * SEQ * DM + (size_t)h * HD;
    const int lr = tid >> 4, lc = (tid & 15) * 4;          // 8 rows x 64 cols/iter

    // ---- Stage Q tile (128 rows) ----
    {
        const float* Qg = Qb + base + (size_t)(qt * 128) * DM;
        #pragma unroll
        for (int i = 0; i < 16; i++) {
            const int r = lr + i * 8;
            float4 v = *(const float4*)(Qg + (size_t)r * DM + lc);
            *(uint4*)&Qs[r][lc] = make_uint4(f2tf(v.x), f2tf(v.y), f2tf(v.z), f2tf(v.w));
        }
    }

    float m[2][2], l[2][2], O[2][8][4];
    #pragma unroll
    for (int mt = 0; mt < 2; mt++) {
        m[mt][0] = NEG_INF; m[mt][1] = NEG_INF;
        l[mt][0] = 0.f;     l[mt][1] = 0.f;
        #pragma unroll
        for (int nt = 0; nt < 8; nt++)
            #pragma unroll
            for (int i = 0; i < 4; i++) O[mt][nt][i] = 0.f;
    }

    const int ntiles = 2 * qt + 2;
    for (int kt = 0; kt < ntiles; kt++) {
        if (kt) __syncthreads();       // prev tile's smem reads done

        // ---- stage K and V tiles (64 kv rows) ----
        const float* Kg = Kb + base + (size_t)(kt * 64) * DM;
        const float* Vg = Vb + base + (size_t)(kt * 64) * DM;
        #pragma unroll
        for (int i = 0; i < 8; i++) {
            const int r = lr + i * 8;
            float4 kv = *(const float4*)(Kg + (size_t)r * DM + lc);
            *(uint4*)&Ks[r][lc] = make_uint4(f2tf(kv.x), f2tf(kv.y), f2tf(kv.z), f2tf(kv.w));
            float4 vv = *(const float4*)(Vg + (size_t)r * DM + lc);
            *(uint4*)&Vs[r][lc] = make_uint4(f2tf(vv.x), f2tf(vv.y), f2tf(vv.z), f2tf(vv.w));
        }
        __syncthreads();               // Qs(kt=0)/Ks/Vs ready

        // ---- S = Q @ K^T (32x64 per warp, 2 m-tiles share K frags) ----
        float S[2][8][4];
        #pragma unroll
        for (int mt = 0; mt < 2; mt++)
            #pragma unroll
            for (int nt = 0; nt < 8; nt++)
                #pragma unroll
                for (int i = 0; i < 4; i++) S[mt][nt][i] = 0.f;

        #pragma unroll
        for (int k8 = 0; k8 < 8; k8++) {
            unsigned qf[2][4];
            #pragma unroll
            for (int mt = 0; mt < 2; mt++) {
                const int r = wb + mt * 16 + lg;
                qf[mt][0] = Qs[r    ][k8 * 8 + la3];
                qf[mt][1] = Qs[r + 8][k8 * 8 + la3];
                qf[mt][2] = Qs[r    ][k8 * 8 + la3 + 4];
                qf[mt][3] = Qs[r + 8][k8 * 8 + la3 + 4];
            }
            #pragma unroll
            for (int nt = 0; nt < 8; nt++) {
                unsigned b0 = Ks[nt * 8 + lg][k8 * 8 + la3];
                unsigned b1 = Ks[nt * 8 + lg][k8 * 8 + la3 + 4];
                mma8(S[0][nt], qf[0], b0, b1);
                mma8(S[1][nt], qf[1], b0, b1);
            }
        }

        // ---- Causal mask (tiles at/after the diagonal band) ----
        if (kt >= 2 * qt) {
            #pragma unroll
            for (int mt = 0; mt < 2; mt++) {
                const int rg0 = qt * 128 + wb + mt * 16 + lg;
                const int rg1 = rg0 + 8;
                #pragma unroll
                for (int nt = 0; nt < 8; nt++) {
                    const int cg = kt * 64 + nt * 8 + 2 * la3;
                    if (cg     > rg0) S[mt][nt][0] = NEG_INF;
                    if (cg + 1 > rg0) S[mt][nt][1] = NEG_INF;
                    if (cg     > rg1) S[mt][nt][2] = NEG_INF;
                    if (cg + 1 > rg1) S[mt][nt][3] = NEG_INF;
                }
            }
        }

        // ---- Online softmax per m-tile (rows lg / lg+8; 4-lane quads) ----
        #pragma unroll
        for (int mt = 0; mt < 2; mt++) {
            float mx0 = NEG_INF, mx1 = NEG_INF;
            #pragma unroll
            for (int nt = 0; nt < 8; nt++) {
                mx0 = fmaxf(mx0, fmaxf(S[mt][nt][0], S[mt][nt][1]));
                mx1 = fmaxf(mx1, fmaxf(S[mt][nt][2], S[mt][nt][3]));
            }
            mx0 = fmaxf(mx0, __shfl_xor_sync(0xffffffffu, mx0, 1));
            mx0 = fmaxf(mx0, __shfl_xor_sync(0xffffffffu, mx0, 2));
            mx1 = fmaxf(mx1, __shfl_xor_sync(0xffffffffu, mx1, 1));
            mx1 = fmaxf(mx1, __shfl_xor_sync(0xffffffffu, mx1, 2));
            const float mn0 = fmaxf(m[mt][0], mx0), mn1 = fmaxf(m[mt][1], mx1);
            const float al0 = __expf(m[mt][0] - mn0), al1 = __expf(m[mt][1] - mn1);
            float rs0 = 0.f, rs1 = 0.f;
            #pragma unroll
            for (int nt = 0; nt < 8; nt++) {
                S[mt][nt][0] = __expf(S[mt][nt][0] - mn0);
                S[mt][nt][1] = __expf(S[mt][nt][1] - mn0);
                S[mt][nt][2] = __expf(S[mt][nt][2] - mn1);
                S[mt][nt][3] = __expf(S[mt][nt][3] - mn1);
                rs0 += S[mt][nt][0] + S[mt][nt][1];
                rs1 += S[mt][nt][2] + S[mt][nt][3];
            }
            rs0 += __shfl_xor_sync(0xffffffffu, rs0, 1);
            rs0 += __shfl_xor_sync(0xffffffffu, rs0, 2);
            rs1 += __shfl_xor_sync(0xffffffffu, rs1, 1);
            rs1 += __shfl_xor_sync(0xffffffffu, rs1, 2);
            l[mt][0] = l[mt][0] * al0 + rs0;  m[mt][0] = mn0;
            l[mt][1] = l[mt][1] * al1 + rs1;  m[mt][1] = mn1;
            #pragma unroll
            for (int nt = 0; nt < 8; nt++) {
                O[mt][nt][0] *= al0;  O[mt][nt][1] *= al0;
                O[mt][nt][2] *= al1;  O[mt][nt][3] *= al1;
            }
            // P -> per-warp-private smem rows
            #pragma unroll
            for (int nt = 0; nt < 8; nt++) {
                const int r = wb + mt * 16 + lg;
                *(uint2*)&Ps[r    ][nt * 8 + 2 * la3] =
                    make_uint2(f2tf(S[mt][nt][0]), f2tf(S[mt][nt][1]));
                *(uint2*)&Ps[r + 8][nt * 8 + 2 * la3] =
                    make_uint2(f2tf(S[mt][nt][2]), f2tf(S[mt][nt][3]));
            }
        }
        __syncwarp();

        // ---- O += P @ V (V frags shared across 2 m-tiles) ----
        #pragma unroll
        for (int k8 = 0; k8 < 8; k8++) {
            unsigned pf[2][4];
            #pragma unroll
            for (int mt = 0; mt < 2; mt++) {
                const int r = wb + mt * 16 + lg;
                pf[mt][0] = Ps[r    ][k8 * 8 + la3];
                pf[mt][1] = Ps[r + 8][k8 * 8 + la3];
                pf[mt][2] = Ps[r    ][k8 * 8 + la3 + 4];
                pf[mt][3] = Ps[r + 8][k8 * 8 + la3 + 4];
            }
            #pragma unroll
            for (int nt = 0; nt < 8; nt++) {
                unsigned b0 = Vs[k8 * 8 + la3    ][nt * 8 + lg];
                unsigned b1 = Vs[k8 * 8 + la3 + 4][nt * 8 + lg];
                mma8(O[0][nt], pf[0], b0, b1);
                mma8(O[1][nt], pf[1], b0, b1);
            }
        }
    }

    // ---- Epilogue ----
    float* Og = Ob + base + (size_t)(qt * 128) * DM;
    #pragma unroll
    for (int mt = 0; mt < 2; mt++) {
        const float il0 = 1.0f / l[mt][0], il1 = 1.0f / l[mt][1];
        const int r = wb + mt * 16 + lg;
        #pragma unroll
        for (int nt = 0; nt < 8; nt++) {
            const int col = nt * 8 + 2 * la3;
            *(float2*)(Og + (size_t)(r    ) * DM + col) =
                make_float2(O[mt][nt][0] * il0, O[mt][nt][1] * il0);
            *(float2*)(Og + (size_t)(r + 8) * DM + col) =
                make_float2(O[mt][nt][2] * il1, O[mt][nt][3] * il1);
        }
    }
}

// ---------------------------------------------------------------------------
extern "C" void kernel_launch(void* const* d_in, const int* in_sizes, int n_in,
                              void* d_out, int out_size)
{
    const float* x  = (const float*)d_in[0];
    const float* Ww = (const float*)d_in[1];
    const float* Wb = (const float*)d_in[2];
    const float* Ow = (const float*)d_in[3];
    const float* Ob = (const float*)d_in[4];
    float* out = (float*)d_out;

    float *q, *k, *v, *c1, *c2;
    cudaGetSymbolAddress((void**)&q,  g_q);
    cudaGetSymbolAddress((void**)&k,  g_k);
    cudaGetSymbolAddress((void**)&v,  g_v);
    cudaGetSymbolAddress((void**)&c1, g_c1);
    cudaGetSymbolAddress((void**)&c2, g_c2);

    cudaFuncSetAttribute(attn_tc,
                         cudaFuncAttributeMaxDynamicSharedMemorySize, ATTN_SMEM);

    // 1) QKV projection + bias, scatter into q/k/v (k pre-scaled by 1/8)
    dim3 g1(3 * DM / 128, MROWS / 128);
    gemm_tc<1><<<g1, 256>>>(x, Ww, Wb, nullptr, MROWS, 3 * DM, DM, q, k, v);

    // 2-4) repeated causal attention (Q tile 128 rows)
    dim3 ga(SEQ / 128, NH, BATCH);
    attn_tc<<<ga, 128, ATTN_SMEM>>>(q,  k, v, c1);
    attn_tc<<<ga, 128, ATTN_SMEM>>>(c1, k, v, c2);
    attn_tc<<<ga, 128, ATTN_SMEM>>>(c2, k, v, c1);

    // 5) output projection + bias
    dim3 g2(DM / 128, MROWS / 128);
    gemm_tc<0><<<g2, 256>>>(c1, Ow, Ob, out, MROWS, DM, DM,
                            nullptr, nullptr, nullptr);
}

// round 6
// speedup vs baseline: 1.6473x; 1.6201x over previous
#include <cuda_runtime.h>
#include <cuda_fp16.h>

#define DM    1024
#define NH    16
#define HD    64
#define BATCH 2
#define SEQ   2048
#define MROWS (BATCH*SEQ)      // 4096

// Scratch (device globals, fp16 — no allocation allowed)
__device__ __half g_q [MROWS*DM];
__device__ __half g_k [MROWS*DM];   // pre-scaled by 1/sqrt(HD)
__device__ __half g_v [MROWS*DM];
__device__ __half g_c1[MROWS*DM];
__device__ __half g_c2[MROWS*DM];

__device__ __forceinline__ unsigned pack2(float a, float b) {
    __half2 h = __floats2half2_rn(a, b);
    return *(unsigned*)&h;
}
__device__ __forceinline__ unsigned su32(const void* p) {
    return (unsigned)__cvta_generic_to_shared(p);
}
__device__ __forceinline__ void mma16(float* d, const unsigned* a,
                                      unsigned b0, unsigned b1) {
    asm volatile(
        "mma.sync.aligned.m16n8k16.row.col.f32.f16.f16.f32 "
        "{%0,%1,%2,%3}, {%4,%5,%6,%7}, {%8,%9}, {%0,%1,%2,%3};"
        : "+f"(d[0]), "+f"(d[1]), "+f"(d[2]), "+f"(d[3])
        : "r"(a[0]), "r"(a[1]), "r"(a[2]), "r"(a[3]), "r"(b0), "r"(b1));
}
__device__ __forceinline__ void ldsm4(unsigned& r0, unsigned& r1,
                                      unsigned& r2, unsigned& r3, unsigned a) {
    asm volatile("ldmatrix.sync.aligned.m8n8.x4.shared.b16 {%0,%1,%2,%3}, [%4];"
        : "=r"(r0), "=r"(r1), "=r"(r2), "=r"(r3) : "r"(a));
}
__device__ __forceinline__ void ldsm4t(unsigned& r0, unsigned& r1,
                                       unsigned& r2, unsigned& r3, unsigned a) {
    asm volatile("ldmatrix.sync.aligned.m8n8.x4.trans.shared.b16 {%0,%1,%2,%3}, [%4];"
        : "=r"(r0), "=r"(r1), "=r"(r2), "=r"(r3) : "r"(a));
}

// ---------------------------------------------------------------------------
// FP16 tensor-core GEMM: C[M,N] = A[M,K] @ Bw[N,K]^T + bias[N]
// MODE 0: f32 write to C; MODE 1: qkv scatter to fp16 buffers (k * 0.125)
// INA 0: A is f32; INA 1: A is fp16.
// CTA 128x128, 256 threads (8 warps 4x2), warp 32x64, kc=16.
// ---------------------------------------------------------------------------
template<int MODE, int INA>
__global__ __launch_bounds__(256, 2)
void gemm_h(const void* __restrict__ Av, const float* __restrict__ Bw,
            const float* __restrict__ bias, float* __restrict__ C,
            int M, int N, int K,
            __half* __restrict__ qo, __half* __restrict__ ko,
            __half* __restrict__ vo)
{
    __shared__ __half As[128][24];   // stride 24 halfs = 12 words
    __shared__ __half Bs[128][24];

    const int tid = threadIdx.x;
    const int wid = tid >> 5, lane = tid & 31;
    const int lg = lane >> 2, la3 = lane & 3;
    const int wm = wid & 3, wn = wid >> 2;
    const int bm = blockIdx.y * 128, bn = blockIdx.x * 128;

    float acc[2][8][4];
    #pragma unroll
    for (int mt = 0; mt < 2; mt++)
        #pragma unroll
        for (int nt = 0; nt < 8; nt++)
            #pragma unroll
            for (int i = 0; i < 4; i++) acc[mt][nt][i] = 0.f;

    const int lrow = tid >> 1, lcolh = (tid & 1) * 8;   // 128 rows x 16 halfs
    const float* Afp = (const float*)Av + (size_t)(bm + lrow) * K + lcolh;
    const __half* Ahp = (const __half*)Av + (size_t)(bm + lrow) * K + lcolh;
    const float* Bp = Bw + (size_t)(bn + lrow) * K + lcolh;

    float4 pa0, pa1, pb0, pb1;
    uint4 ua;
    if (INA == 0) { pa0 = *(const float4*)(Afp); pa1 = *(const float4*)(Afp + 4); }
    else          { ua = *(const uint4*)(Ahp); }
    pb0 = *(const float4*)(Bp); pb1 = *(const float4*)(Bp + 4);

    for (int k0 = 0; k0 < K; k0 += 16) {
        __syncthreads();
        if (INA == 0)
            *(uint4*)&As[lrow][lcolh] = make_uint4(
                pack2(pa0.x, pa0.y), pack2(pa0.z, pa0.w),
                pack2(pa1.x, pa1.y), pack2(pa1.z, pa1.w));
        else
            *(uint4*)&As[lrow][lcolh] = ua;
        *(uint4*)&Bs[lrow][lcolh] = make_uint4(
            pack2(pb0.x, pb0.y), pack2(pb0.z, pb0.w),
            pack2(pb1.x, pb1.y), pack2(pb1.z, pb1.w));
        if (k0 + 16 < K) {
            if (INA == 0) { pa0 = *(const float4*)(Afp + k0 + 16);
                            pa1 = *(const float4*)(Afp + k0 + 20); }
            else          { ua = *(const uint4*)(Ahp + k0 + 16); }
            pb0 = *(const float4*)(Bp + k0 + 16);
            pb1 = *(const float4*)(Bp + k0 + 20);
        }
        __syncthreads();

        unsigned af[2][4], bf[8][2];
        #pragma unroll
        for (int mt = 0; mt < 2; mt++) {
            const int r = wm * 32 + mt * 16 + lg;
            af[mt][0] = *(const unsigned*)&As[r    ][2 * la3];
            af[mt][1] = *(const unsigned*)&As[r + 8][2 * la3];
            af[mt][2] = *(const unsigned*)&As[r    ][2 * la3 + 8];
            af[mt][3] = *(const unsigned*)&As[r + 8][2 * la3 + 8];
        }
        #pragma unroll
        for (int nt = 0; nt < 8; nt++) {
            const int n = wn * 64 + nt * 8 + lg;
            bf[nt][0] = *(const unsigned*)&Bs[n][2 * la3];
            bf[nt][1] = *(const unsigned*)&Bs[n][2 * la3 + 8];
        }
        #pragma unroll
        for (int mt = 0; mt < 2; mt++)
            #pragma unroll
            for (int nt = 0; nt < 8; nt++)
                mma16(acc[mt][nt], af[mt], bf[nt][0], bf[nt][1]);
    }

    #pragma unroll
    for (int mt = 0; mt < 2; mt++)
        #pragma unroll
        for (int nt = 0; nt < 8; nt++) {
            const int row0 = bm + wm * 32 + mt * 16 + lg;
            const int col  = bn + wn * 64 + nt * 8 + 2 * la3;
            float v0 = acc[mt][nt][0] + bias[col];
            float v1 = acc[mt][nt][1] + bias[col + 1];
            float v2 = acc[mt][nt][2] + bias[col];
            float v3 = acc[mt][nt][3] + bias[col + 1];
            if (MODE == 0) {
                *(float2*)&C[(size_t)row0 * N + col]       = make_float2(v0, v1);
                *(float2*)&C[(size_t)(row0 + 8) * N + col] = make_float2(v2, v3);
            } else {
                const int g = col >> 10, rem = col & 1023;
                if (g == 1) { v0 *= 0.125f; v1 *= 0.125f; v2 *= 0.125f; v3 *= 0.125f; }
                __half* dst = (g == 0) ? qo : (g == 1) ? ko : vo;
                *(unsigned*)&dst[(size_t)row0 * DM + rem]       = pack2(v0, v1);
                *(unsigned*)&dst[(size_t)(row0 + 8) * DM + rem] = pack2(v2, v3);
            }
        }
}

// ---------------------------------------------------------------------------
// FP16 tensor-core causal flash attention.
// CTA: 256 threads (8 warps), Q tile 128 rows (16/warp), kv tile 64.
// Q fragments via ldmatrix (staged once, buffer reused for K/V),
// K B-frags via ldmatrix, V B-frags via ldmatrix.trans,
// P stays in registers (C-frag == A-frag layout in fp16).
// smem 18.4KB static.
// ---------------------------------------------------------------------------
#define AST 72   // half stride = 36 words: conflict-free ldsm + staging

__global__ __launch_bounds__(256, 2)
void attn_h(const __half* __restrict__ Qb, const __half* __restrict__ Kb,
            const __half* __restrict__ Vb, __half* __restrict__ Ob)
{
    __shared__ __half sbuf[128 * AST];          // Qbuf[128] == Ks[64]+Vs[64]
    __half (*Qbuf)[AST] = (__half(*)[AST])sbuf;
    __half (*Ks)[AST] = (__half(*)[AST])sbuf;
    __half (*Vs)[AST] = (__half(*)[AST])(sbuf + 64 * AST);

    const int qt = (int)gridDim.x - 1 - (int)blockIdx.x;   // long rows first
    const int h = blockIdx.y, b = blockIdx.z;
    const int tid = threadIdx.x, wid = tid >> 5, lane = tid & 31;
    const int lg = lane >> 2, la3 = lane & 3;
    const int wb = wid * 16;
    const float NEG_INF = __int_as_float(0xff800000);

    const size_t base = (size_t)b * SEQ * DM + (size_t)h * HD;
    const int sr = tid >> 3, sc = (tid & 7) * 8;   // staging: 32 rows x 64 halfs

    // ---- Stage Q tile (128x64 halfs) into shared buffer ----
    {
        const __half* Qg = Qb + base + (size_t)(qt * 128) * DM;
        #pragma unroll
        for (int p = 0; p < 4; p++) {
            const int r = sr + p * 32;
            *(uint4*)&Qbuf[r][sc] = *(const uint4*)(Qg + (size_t)r * DM + sc);
        }
    }
    __syncthreads();

    // ---- Q fragments via ldmatrix.x4 (register-resident) ----
    unsigned Qf[4][4];
    {
        unsigned qaddr = su32(&Qbuf[wb + (lane & 15)][(lane >> 4) * 8]);
        #pragma unroll
        for (int k16 = 0; k16 < 4; k16++)
            ldsm4(Qf[k16][0], Qf[k16][1], Qf[k16][2], Qf[k16][3],
                  qaddr + k16 * 32);
    }
    __syncthreads();   // Qbuf free for K/V reuse

    const unsigned kaddr = su32(Ks) +
        ((lane & 7) + ((lane >> 4) << 3)) * (AST * 2) + (lane & 8) * 2;
    const unsigned vaddr = su32(Vs) +
        (lane & 15) * (AST * 2) + (lane >> 4) * 16;

    float m0 = NEG_INF, m1 = NEG_INF, l0 = 0.f, l1 = 0.f;
    float O[8][4];
    #pragma unroll
    for (int nt = 0; nt < 8; nt++)
        #pragma unroll
        for (int i = 0; i < 4; i++) O[nt][i] = 0.f;

    const int ntiles = 2 * qt + 2;
    for (int kt = 0; kt < ntiles; kt++) {
        if (kt) __syncthreads();

        // ---- stage K and V (64x64 halfs each, direct fp16 copy) ----
        const __half* Kg = Kb + base + (size_t)(kt * 64) * DM;
        const __half* Vg = Vb + base + (size_t)(kt * 64) * DM;
        #pragma unroll
        for (int p = 0; p < 2; p++) {
            const int r = sr + p * 32;
            *(uint4*)&Ks[r][sc] = *(const uint4*)(Kg + (size_t)r * DM + sc);
            *(uint4*)&Vs[r][sc] = *(const uint4*)(Vg + (size_t)r * DM + sc);
        }
        __syncthreads();

        // ---- S = Q @ K^T (16x64 per warp; 32 MMAs, 16 LDSM) ----
        float S[8][4];
        #pragma unroll
        for (int nt = 0; nt < 8; nt++)
            #pragma unroll
            for (int i = 0; i < 4; i++) S[nt][i] = 0.f;

        #pragma unroll
        for (int k16 = 0; k16 < 4; k16++)
            #pragma unroll
            for (int n16 = 0; n16 < 4; n16++) {
                unsigned r0, r1, r2, r3;
                ldsm4(r0, r1, r2, r3,
                      kaddr + n16 * 16 * (AST * 2) + k16 * 32);
                mma16(S[2 * n16    ], Qf[k16], r0, r1);
                mma16(S[2 * n16 + 1], Qf[k16], r2, r3);
            }

        // ---- Causal mask (diagonal band tiles only) ----
        if (kt >= 2 * qt) {
            const int rg0 = qt * 128 + wb + lg, rg1 = rg0 + 8;
            #pragma unroll
            for (int nt = 0; nt < 8; nt++) {
                const int cg = kt * 64 + nt * 8 + 2 * la3;
                if (cg     > rg0) S[nt][0] = NEG_INF;
                if (cg + 1 > rg0) S[nt][1] = NEG_INF;
                if (cg     > rg1) S[nt][2] = NEG_INF;
                if (cg + 1 > rg1) S[nt][3] = NEG_INF;
            }
        }

        // ---- Online softmax (rows lg / lg+8; 4-lane quads) ----
        float mx0 = NEG_INF, mx1 = NEG_INF;
        #pragma unroll
        for (int nt = 0; nt < 8; nt++) {
            mx0 = fmaxf(mx0, fmaxf(S[nt][0], S[nt][1]));
            mx1 = fmaxf(mx1, fmaxf(S[nt][2], S[nt][3]));
        }
        mx0 = fmaxf(mx0, __shfl_xor_sync(0xffffffffu, mx0, 1));
        mx0 = fmaxf(mx0, __shfl_xor_sync(0xffffffffu, mx0, 2));
        mx1 = fmaxf(mx1, __shfl_xor_sync(0xffffffffu, mx1, 1));
        mx1 = fmaxf(mx1, __shfl_xor_sync(0xffffffffu, mx1, 2));
        const float mn0 = fmaxf(m0, mx0), mn1 = fmaxf(m1, mx1);
        const float al0 = __expf(m0 - mn0), al1 = __expf(m1 - mn1);
        float rs0 = 0.f, rs1 = 0.f;
        #pragma unroll
        for (int nt = 0; nt < 8; nt++) {
            S[nt][0] = __expf(S[nt][0] - mn0);
            S[nt][1] = __expf(S[nt][1] - mn0);
            S[nt][2] = __expf(S[nt][2] - mn1);
            S[nt][3] = __expf(S[nt][3] - mn1);
            rs0 += S[nt][0] + S[nt][1];
            rs1 += S[nt][2] + S[nt][3];
        }
        rs0 += __shfl_xor_sync(0xffffffffu, rs0, 1);
        rs0 += __shfl_xor_sync(0xffffffffu, rs0, 2);
        rs1 += __shfl_xor_sync(0xffffffffu, rs1, 1);
        rs1 += __shfl_xor_sync(0xffffffffu, rs1, 2);
        l0 = l0 * al0 + rs0;  m0 = mn0;
        l1 = l1 * al1 + rs1;  m1 = mn1;
        #pragma unroll
        for (int nt = 0; nt < 8; nt++) {
            O[nt][0] *= al0;  O[nt][1] *= al0;
            O[nt][2] *= al1;  O[nt][3] *= al1;
        }

        // ---- P fragments: direct from S registers (C-frag == A-frag) ----
        unsigned Pf[4][4];
        #pragma unroll
        for (int k16 = 0; k16 < 4; k16++) {
            Pf[k16][0] = pack2(S[2 * k16    ][0], S[2 * k16    ][1]);
            Pf[k16][1] = pack2(S[2 * k16    ][2], S[2 * k16    ][3]);
            Pf[k16][2] = pack2(S[2 * k16 + 1][0], S[2 * k16 + 1][1]);
            Pf[k16][3] = pack2(S[2 * k16 + 1][2], S[2 * k16 + 1][3]);
        }

        // ---- O += P @ V (V via ldmatrix.trans; 32 MMAs, 16 LDSM) ----
        #pragma unroll
        for (int k16 = 0; k16 < 4; k16++)
            #pragma unroll
            for (int n16 = 0; n16 < 4; n16++) {
                unsigned r0, r1, r2, r3;
                ldsm4t(r0, r1, r2, r3,
                       vaddr + k16 * 16 * (AST * 2) + n16 * 32);
                mma16(O[2 * n16    ], Pf[k16], r0, r1);
                mma16(O[2 * n16 + 1], Pf[k16], r2, r3);
            }
    }

    // ---- Epilogue (fp16 context out) ----
    __half* Og = Ob + base + (size_t)(qt * 128) * DM;
    const float il0 = 1.0f / l0, il1 = 1.0f / l1;
    const int r0 = wb + lg, r1 = r0 + 8;
    #pragma unroll
    for (int nt = 0; nt < 8; nt++) {
        const int col = nt * 8 + 2 * la3;
        *(unsigned*)&Og[(size_t)r0 * DM + col] =
            pack2(O[nt][0] * il0, O[nt][1] * il0);
        *(unsigned*)&Og[(size_t)r1 * DM + col] =
            pack2(O[nt][2] * il1, O[nt][3] * il1);
    }
}

// ---------------------------------------------------------------------------
extern "C" void kernel_launch(void* const* d_in, const int* in_sizes, int n_in,
                              void* d_out, int out_size)
{
    const float* x  = (const float*)d_in[0];
    const float* Ww = (const float*)d_in[1];
    const float* Wb = (const float*)d_in[2];
    const float* Ow = (const float*)d_in[3];
    const float* Ob = (const float*)d_in[4];
    float* out = (float*)d_out;

    __half *q, *k, *v, *c1, *c2;
    cudaGetSymbolAddress((void**)&q,  g_q);
    cudaGetSymbolAddress((void**)&k,  g_k);
    cudaGetSymbolAddress((void**)&v,  g_v);
    cudaGetSymbolAddress((void**)&c1, g_c1);
    cudaGetSymbolAddress((void**)&c2, g_c2);

    // 1) QKV projection + bias -> fp16 q/k/v (k pre-scaled by 1/8)
    dim3 g1(3 * DM / 128, MROWS / 128);
    gemm_h<1, 0><<<g1, 256>>>(x, Ww, Wb, nullptr, MROWS, 3 * DM, DM, q, k, v);

    // 2-4) repeated causal attention (fp16 in/out)
    dim3 ga(SEQ / 128, NH, BATCH);
    attn_h<<<ga, 256>>>(q,  k, v, c1);
    attn_h<<<ga, 256>>>(c1, k, v, c2);
    attn_h<<<ga, 256>>>(c2, k, v, c1);

    // 5) output projection + bias (fp16 A -> f32 out)
    dim3 g2(DM / 128, MROWS / 128);
    gemm_h<0, 1><<<g2, 256>>>(c1, Ow, Ob, out, MROWS, DM, DM,
                              nullptr, nullptr, nullptr);
}

// round 7
// speedup vs baseline: 1.8871x; 1.1455x over previous
#include <cuda_runtime.h>
#include <cuda_fp16.h>

#define DM    1024
#define NH    16
#define HD    64
#define BATCH 2
#define SEQ   2048
#define MROWS (BATCH*SEQ)      // 4096

// log2(e)/sqrt(64) folded into K: scores come out in log2 units
#define KSCALE 0.1803368801111137f

// Scratch (device globals, fp16 — no allocation allowed)
__device__ __half g_q [MROWS*DM];
__device__ __half g_k [MROWS*DM];
__device__ __half g_v [MROWS*DM];
__device__ __half g_c1[MROWS*DM];
__device__ __half g_c2[MROWS*DM];

__device__ __forceinline__ unsigned pack2(float a, float b) {
    __half2 h = __floats2half2_rn(a, b);
    return *(unsigned*)&h;
}
__device__ __forceinline__ unsigned su32(const void* p) {
    return (unsigned)__cvta_generic_to_shared(p);
}
__device__ __forceinline__ float ex2f(float x) {
    float r; asm("ex2.approx.f32 %0, %1;" : "=f"(r) : "f"(x)); return r;
}
__device__ __forceinline__ unsigned hex2(unsigned x) {
    unsigned r; asm("ex2.approx.f16x2 %0, %1;" : "=r"(r) : "r"(x)); return r;
}
__device__ __forceinline__ void mma16(float* d, const unsigned* a,
                                      unsigned b0, unsigned b1) {
    asm volatile(
        "mma.sync.aligned.m16n8k16.row.col.f32.f16.f16.f32 "
        "{%0,%1,%2,%3}, {%4,%5,%6,%7}, {%8,%9}, {%0,%1,%2,%3};"
        : "+f"(d[0]), "+f"(d[1]), "+f"(d[2]), "+f"(d[3])
        : "r"(a[0]), "r"(a[1]), "r"(a[2]), "r"(a[3]), "r"(b0), "r"(b1));
}
__device__ __forceinline__ void ldsm4(unsigned& r0, unsigned& r1,
                                      unsigned& r2, unsigned& r3, unsigned a) {
    asm volatile("ldmatrix.sync.aligned.m8n8.x4.shared.b16 {%0,%1,%2,%3}, [%4];"
        : "=r"(r0), "=r"(r1), "=r"(r2), "=r"(r3) : "r"(a));
}
__device__ __forceinline__ void ldsm4t(unsigned& r0, unsigned& r1,
                                       unsigned& r2, unsigned& r3, unsigned a) {
    asm volatile("ldmatrix.sync.aligned.m8n8.x4.trans.shared.b16 {%0,%1,%2,%3}, [%4];"
        : "=r"(r0), "=r"(r1), "=r"(r2), "=r"(r3) : "r"(a));
}
__device__ __forceinline__ void cpa16(unsigned dst, const void* src) {
    asm volatile("cp.async.ca.shared.global [%0], [%1], 16;"
        :: "r"(dst), "l"(src));
}
__device__ __forceinline__ void cpa_commit() {
    asm volatile("cp.async.commit_group;");
}
__device__ __forceinline__ void cpa_wait0() {
    asm volatile("cp.async.wait_group 0;" ::: "memory");
}

// ---------------------------------------------------------------------------
// FP16 tensor-core GEMM: C[M,N] = A[M,K] @ Bw[N,K]^T + bias[N]
// MODE 0: f32 write to C; MODE 1: qkv scatter to fp16 buffers (k * KSCALE)
// INA 0: A is f32; INA 1: A is fp16.
// CTA 128x128, 256 threads (8 warps 4x2), warp 32x64, kc=32, ldmatrix frags.
// ---------------------------------------------------------------------------
template<int MODE, int INA>
__global__ __launch_bounds__(256, 2)
void gemm_h(const void* __restrict__ Av, const float* __restrict__ Bw,
            const float* __restrict__ bias, float* __restrict__ C,
            int M, int N, int K,
            __half* __restrict__ qo, __half* __restrict__ ko,
            __half* __restrict__ vo)
{
    __shared__ __half As[128][40];   // kc=32 + pad 8
    __shared__ __half Bs[128][40];

    const int tid = threadIdx.x;
    const int wid = tid >> 5, lane = tid & 31;
    const int lg = lane >> 2, la3 = lane & 3;
    const int wm = wid & 3, wn = wid >> 2;
    const int bm = blockIdx.y * 128, bn = blockIdx.x * 128;

    float acc[2][8][4];
    #pragma unroll
    for (int mt = 0; mt < 2; mt++)
        #pragma unroll
        for (int nt = 0; nt < 8; nt++)
            #pragma unroll
            for (int i = 0; i < 4; i++) acc[mt][nt][i] = 0.f;

    const int lrow = tid >> 1, lcolh = (tid & 1) * 16;  // 128 rows x 32 halfs
    const float* Afp = (const float*)Av + (size_t)(bm + lrow) * K + lcolh;
    const __half* Ahp = (const __half*)Av + (size_t)(bm + lrow) * K + lcolh;
    const float* Bp = Bw + (size_t)(bn + lrow) * K + lcolh;

    float4 pa[4], pb[4];
    uint4 ua[2];
    if (INA == 0) {
        #pragma unroll
        for (int i = 0; i < 4; i++) pa[i] = ((const float4*)Afp)[i];
    } else {
        ua[0] = ((const uint4*)Ahp)[0]; ua[1] = ((const uint4*)Ahp)[1];
    }
    #pragma unroll
    for (int i = 0; i < 4; i++) pb[i] = ((const float4*)Bp)[i];

    const unsigned a_frag_base = su32(&As[wm * 32 + (lane & 15)][(lane >> 4) * 8]);
    const unsigned b_frag_base = su32(&Bs[wn * 64 + ((lane & 7) + ((lane >> 4) << 3))][0])
                                 + (lane & 8) * 2;

    for (int k0 = 0; k0 < K; k0 += 32) {
        __syncthreads();
        if (INA == 0) {
            *(uint4*)&As[lrow][lcolh] = make_uint4(
                pack2(pa[0].x, pa[0].y), pack2(pa[0].z, pa[0].w),
                pack2(pa[1].x, pa[1].y), pack2(pa[1].z, pa[1].w));
            *(uint4*)&As[lrow][lcolh + 8] = make_uint4(
                pack2(pa[2].x, pa[2].y), pack2(pa[2].z, pa[2].w),
                pack2(pa[3].x, pa[3].y), pack2(pa[3].z, pa[3].w));
        } else {
            *(uint4*)&As[lrow][lcolh]     = ua[0];
            *(uint4*)&As[lrow][lcolh + 8] = ua[1];
        }
        *(uint4*)&Bs[lrow][lcolh] = make_uint4(
            pack2(pb[0].x, pb[0].y), pack2(pb[0].z, pb[0].w),
            pack2(pb[1].x, pb[1].y), pack2(pb[1].z, pb[1].w));
        *(uint4*)&Bs[lrow][lcolh + 8] = make_uint4(
            pack2(pb[2].x, pb[2].y), pack2(pb[2].z, pb[2].w),
            pack2(pb[3].x, pb[3].y), pack2(pb[3].z, pb[3].w));
        if (k0 + 32 < K) {
            if (INA == 0) {
                #pragma unroll
                for (int i = 0; i < 4; i++)
                    pa[i] = *(const float4*)(Afp + k0 + 32 + 4 * i);
            } else {
                ua[0] = *(const uint4*)(Ahp + k0 + 32);
                ua[1] = *(const uint4*)(Ahp + k0 + 40);
            }
            #pragma unroll
            for (int i = 0; i < 4; i++)
                pb[i] = *(const float4*)(Bp + k0 + 32 + 4 * i);
        }
        __syncthreads();

        #pragma unroll
        for (int ks = 0; ks < 2; ks++) {
            unsigned af[2][4];
            #pragma unroll
            for (int mt = 0; mt < 2; mt++)
                ldsm4(af[mt][0], af[mt][1], af[mt][2], af[mt][3],
                      a_frag_base + (mt * 16 * 40 + ks * 16) * 2);
            #pragma unroll
            for (int n16 = 0; n16 < 4; n16++) {
                unsigned r0, r1, r2, r3;
                ldsm4(r0, r1, r2, r3,
                      b_frag_base + (n16 * 16 * 40 + ks * 16) * 2);
                #pragma unroll
                for (int mt = 0; mt < 2; mt++) {
                    mma16(acc[mt][2 * n16    ], af[mt], r0, r1);
                    mma16(acc[mt][2 * n16 + 1], af[mt], r2, r3);
                }
            }
        }
    }

    #pragma unroll
    for (int mt = 0; mt < 2; mt++)
        #pragma unroll
        for (int nt = 0; nt < 8; nt++) {
            const int row0 = bm + wm * 32 + mt * 16 + lg;
            const int col  = bn + wn * 64 + nt * 8 + 2 * la3;
            float v0 = acc[mt][nt][0] + bias[col];
            float v1 = acc[mt][nt][1] + bias[col + 1];
            float v2 = acc[mt][nt][2] + bias[col];
            float v3 = acc[mt][nt][3] + bias[col + 1];
            if (MODE == 0) {
                *(float2*)&C[(size_t)row0 * N + col]       = make_float2(v0, v1);
                *(float2*)&C[(size_t)(row0 + 8) * N + col] = make_float2(v2, v3);
            } else {
                const int g = col >> 10, rem = col & 1023;
                if (g == 1) { v0 *= KSCALE; v1 *= KSCALE; v2 *= KSCALE; v3 *= KSCALE; }
                __half* dst = (g == 0) ? qo : (g == 1) ? ko : vo;
                *(unsigned*)&dst[(size_t)row0 * DM + rem]       = pack2(v0, v1);
                *(unsigned*)&dst[(size_t)(row0 + 8) * DM + rem] = pack2(v2, v3);
            }
        }
}

// ---------------------------------------------------------------------------
// FP16 tensor-core causal flash attention.
// CTA: 256 threads (8 warps), Q tile 128 rows (16/warp), kv tile 64.
// exp2-domain softmax with f16x2 MUFU; row sums via ones-MMA; K/V staged
// through cp.async double buffers. smem 54KB dynamic -> 2 CTAs/SM.
// ---------------------------------------------------------------------------
#define AST 72
#define ATTN_SMEM ((128*AST + 4*64*AST) * 2)
#define ONES2 0x3C003C00u

__global__ __launch_bounds__(256, 2)
void attn_h(const __half* __restrict__ Qb, const __half* __restrict__ Kb,
            const __half* __restrict__ Vb, __half* __restrict__ Ob)
{
    extern __shared__ __half dsm[];
    __half* Qsm = dsm;                         // [128][AST]
    __half* Ksm = dsm + 128 * AST;             // [2][64][AST]
    __half* Vsm = dsm + 128 * AST + 2 * 64 * AST;

    const int qt = (int)gridDim.x - 1 - (int)blockIdx.x;   // long rows first
    const int h = blockIdx.y, b = blockIdx.z;
    const int tid = threadIdx.x, wid = tid >> 5, lane = tid & 31;
    const int lg = lane >> 2, la3 = lane & 3;
    const int wb = wid * 16;
    const float NEG_INF = __int_as_float(0xff800000);

    const size_t base = (size_t)b * SEQ * DM + (size_t)h * HD;
    const int sr = tid >> 3, sc = (tid & 7) * 8;   // 32 rows x 64 halfs /pass
    const unsigned SOFF = 64 * AST * 2;            // stage byte offset

    // ---- issue cp.async for kv tile 0 (stage 0) ----
    {
        const __half* Kg = Kb + base;
        const __half* Vg = Vb + base;
        #pragma unroll
        for (int p = 0; p < 2; p++) {
            const int r = sr + p * 32;
            cpa16(su32(Ksm + r * AST + sc), Kg + (size_t)r * DM + sc);
            cpa16(su32(Vsm + r * AST + sc), Vg + (size_t)r * DM + sc);
        }
        cpa_commit();
    }

    // ---- stage Q tile, then register-resident Q fragments ----
    {
        const __half* Qg = Qb + base + (size_t)(qt * 128) * DM;
        #pragma unroll
        for (int p = 0; p < 4; p++) {
            const int r = sr + p * 32;
            *(uint4*)(Qsm + r * AST + sc) = *(const uint4*)(Qg + (size_t)r * DM + sc);
        }
    }
    __syncthreads();
    unsigned Qf[4][4];
    {
        unsigned qaddr = su32(Qsm + (wb + (lane & 15)) * AST + (lane >> 4) * 8);
        #pragma unroll
        for (int k16 = 0; k16 < 4; k16++)
            ldsm4(Qf[k16][0], Qf[k16][1], Qf[k16][2], Qf[k16][3],
                  qaddr + k16 * 32);
    }

    const unsigned kbase = su32(Ksm) +
        ((lane & 7) + ((lane >> 4) << 3)) * (AST * 2) + (lane & 8) * 2;
    const unsigned vbase = su32(Vsm) +
        (lane & 15) * (AST * 2) + (lane >> 4) * 16;

    float m0 = NEG_INF, m1 = NEG_INF, l0 = 0.f, l1 = 0.f;
    float O[8][4];
    #pragma unroll
    for (int nt = 0; nt < 8; nt++)
        #pragma unroll
        for (int i = 0; i < 4; i++) O[nt][i] = 0.f;

    const int ntiles = 2 * qt + 2;
    for (int kt = 0; kt < ntiles; kt++) {
        const int cur = kt & 1;
        cpa_wait0();
        __syncthreads();   // tile kt visible to all; prev compute done

        // prefetch kv tile kt+1 into the other stage (overlaps compute)
        if (kt + 1 < ntiles) {
            const __half* Kg = Kb + base + (size_t)((kt + 1) * 64) * DM;
            const __half* Vg = Vb + base + (size_t)((kt + 1) * 64) * DM;
            const int s = cur ^ 1;
            #pragma unroll
            for (int p = 0; p < 2; p++) {
                const int r = sr + p * 32;
                cpa16(su32(Ksm) + s * SOFF + (r * AST + sc) * 2,
                      Kg + (size_t)r * DM + sc);
                cpa16(su32(Vsm) + s * SOFF + (r * AST + sc) * 2,
                      Vg + (size_t)r * DM + sc);
            }
            cpa_commit();
        }

        const unsigned kaddr = kbase + cur * SOFF;
        const unsigned vaddr = vbase + cur * SOFF;

        // ---- S = Q @ K^T (16x64 per warp) ----
        float S[8][4];
        #pragma unroll
        for (int nt = 0; nt < 8; nt++)
            #pragma unroll
            for (int i = 0; i < 4; i++) S[nt][i] = 0.f;

        #pragma unroll
        for (int k16 = 0; k16 < 4; k16++)
            #pragma unroll
            for (int n16 = 0; n16 < 4; n16++) {
                unsigned r0, r1, r2, r3;
                ldsm4(r0, r1, r2, r3,
                      kaddr + n16 * 16 * (AST * 2) + k16 * 32);
                mma16(S[2 * n16    ], Qf[k16], r0, r1);
                mma16(S[2 * n16 + 1], Qf[k16], r2, r3);
            }

        // ---- Causal mask (diagonal band tiles only) ----
        if (kt >= 2 * qt) {
            const int rg0 = qt * 128 + wb + lg, rg1 = rg0 + 8;
            #pragma unroll
            for (int nt = 0; nt < 8; nt++) {
                const int cg = kt * 64 + nt * 8 + 2 * la3;
                if (cg     > rg0) S[nt][0] = NEG_INF;
                if (cg + 1 > rg0) S[nt][1] = NEG_INF;
                if (cg     > rg1) S[nt][2] = NEG_INF;
                if (cg + 1 > rg1) S[nt][3] = NEG_INF;
            }
        }

        // ---- Online softmax in log2 domain ----
        float mx0 = NEG_INF, mx1 = NEG_INF;
        #pragma unroll
        for (int nt = 0; nt < 8; nt++) {
            mx0 = fmaxf(mx0, fmaxf(S[nt][0], S[nt][1]));
            mx1 = fmaxf(mx1, fmaxf(S[nt][2], S[nt][3]));
        }
        mx0 = fmaxf(mx0, __shfl_xor_sync(0xffffffffu, mx0, 1));
        mx0 = fmaxf(mx0, __shfl_xor_sync(0xffffffffu, mx0, 2));
        mx1 = fmaxf(mx1, __shfl_xor_sync(0xffffffffu, mx1, 1));
        mx1 = fmaxf(mx1, __shfl_xor_sync(0xffffffffu, mx1, 2));
        const float mn0 = fmaxf(m0, mx0), mn1 = fmaxf(m1, mx1);
        const float al0 = ex2f(m0 - mn0), al1 = ex2f(m1 - mn1);
        m0 = mn0;  m1 = mn1;

        // P fragments = exp2(S - m), computed 2-at-a-time on the MUFU
        unsigned Pf[4][4];
        #pragma unroll
        for (int k16 = 0; k16 < 4; k16++) {
            Pf[k16][0] = hex2(pack2(S[2*k16  ][0] - mn0, S[2*k16  ][1] - mn0));
            Pf[k16][1] = hex2(pack2(S[2*k16  ][2] - mn1, S[2*k16  ][3] - mn1));
            Pf[k16][2] = hex2(pack2(S[2*k16+1][0] - mn0, S[2*k16+1][1] - mn0));
            Pf[k16][3] = hex2(pack2(S[2*k16+1][2] - mn1, S[2*k16+1][3] - mn1));
        }

        // Row sums via ones-MMA (each lane's slot 0/2 = its row's total)
        float ssum[4] = {0.f, 0.f, 0.f, 0.f};
        #pragma unroll
        for (int k16 = 0; k16 < 4; k16++)
            mma16(ssum, Pf[k16], ONES2, ONES2);
        l0 = l0 * al0 + ssum[0];
        l1 = l1 * al1 + ssum[2];

        #pragma unroll
        for (int nt = 0; nt < 8; nt++) {
            O[nt][0] *= al0;  O[nt][1] *= al0;
            O[nt][2] *= al1;  O[nt][3] *= al1;
        }

        // ---- O += P @ V (V via ldmatrix.trans) ----
        #pragma unroll
        for (int k16 = 0; k16 < 4; k16++)
            #pragma unroll
            for (int n16 = 0; n16 < 4; n16++) {
                unsigned r0, r1, r2, r3;
                ldsm4t(r0, r1, r2, r3,
                       vaddr + k16 * 16 * (AST * 2) + n16 * 32);
                mma16(O[2 * n16    ], Pf[k16], r0, r1);
                mma16(O[2 * n16 + 1], Pf[k16], r2, r3);
            }
    }

    // ---- Epilogue (fp16 context out) ----
    __half* Og = Ob + base + (size_t)(qt * 128) * DM;
    const float il0 = 1.0f / l0, il1 = 1.0f / l1;
    const int r0 = wb + lg, r1 = r0 + 8;
    #pragma unroll
    for (int nt = 0; nt < 8; nt++) {
        const int col = nt * 8 + 2 * la3;
        *(unsigned*)&Og[(size_t)r0 * DM + col] =
            pack2(O[nt][0] * il0, O[nt][1] * il0);
        *(unsigned*)&Og[(size_t)r1 * DM + col] =
            pack2(O[nt][2] * il1, O[nt][3] * il1);
    }
}

// ---------------------------------------------------------------------------
extern "C" void kernel_launch(void* const* d_in, const int* in_sizes, int n_in,
                              void* d_out, int out_size)
{
    const float* x  = (const float*)d_in[0];
    const float* Ww = (const float*)d_in[1];
    const float* Wb = (const float*)d_in[2];
    const float* Ow = (const float*)d_in[3];
    const float* Ob = (const float*)d_in[4];
    float* out = (float*)d_out;

    __half *q, *k, *v, *c1, *c2;
    cudaGetSymbolAddress((void**)&q,  g_q);
    cudaGetSymbolAddress((void**)&k,  g_k);
    cudaGetSymbolAddress((void**)&v,  g_v);
    cudaGetSymbolAddress((void**)&c1, g_c1);
    cudaGetSymbolAddress((void**)&c2, g_c2);

    cudaFuncSetAttribute(attn_h,
                         cudaFuncAttributeMaxDynamicSharedMemorySize, ATTN_SMEM);

    // 1) QKV projection + bias -> fp16 q/k/v (k pre-scaled by log2e/8)
    dim3 g1(3 * DM / 128, MROWS / 128);
    gemm_h<1, 0><<<g1, 256>>>(x, Ww, Wb, nullptr, MROWS, 3 * DM, DM, q, k, v);

    // 2-4) repeated causal attention (fp16 in/out)
    dim3 ga(SEQ / 128, NH, BATCH);
    attn_h<<<ga, 256, ATTN_SMEM>>>(q,  k, v, c1);
    attn_h<<<ga, 256, ATTN_SMEM>>>(c1, k, v, c2);
    attn_h<<<ga, 256, ATTN_SMEM>>>(c2, k, v, c1);

    // 5) output projection + bias (fp16 A -> f32 out)
    dim3 g2(DM / 128, MROWS / 128);
    gemm_h<0, 1><<<g2, 256>>>(c1, Ow, Ob, out, MROWS, DM, DM,
                              nullptr, nullptr, nullptr);
}

// round 9
// speedup vs baseline: 2.2356x; 1.1847x over previous
#include <cuda_runtime.h>
#include <cuda_fp16.h>

#define DM    1024
#define NH    16
#define HD    64
#define BATCH 2
#define SEQ   2048
#define MROWS (BATCH*SEQ)      // 4096

// log2(e)/sqrt(64) folded into K: scores come out in log2 units
#define KSCALE 0.1803368801111137f

// Scratch (device globals, fp16 — no allocation allowed)
__device__ __half g_q  [MROWS*DM];
__device__ __half g_k  [MROWS*DM];
__device__ __half g_v  [MROWS*DM];
__device__ __half g_c1 [MROWS*DM];
__device__ __half g_c2 [MROWS*DM];
__device__ __half g_xh [MROWS*DM];       // x   -> fp16
__device__ __half g_wh [3*DM*DM];        // Wqkv -> fp16
__device__ __half g_oh [DM*DM];          // out_w -> fp16

__device__ __forceinline__ unsigned pack2(float a, float b) {
    __half2 h = __floats2half2_rn(a, b);
    return *(unsigned*)&h;
}
__device__ __forceinline__ unsigned su32(const void* p) {
    return (unsigned)__cvta_generic_to_shared(p);
}
__device__ __forceinline__ float ex2f(float x) {
    float r; asm("ex2.approx.f32 %0, %1;" : "=f"(r) : "f"(x)); return r;
}
__device__ __forceinline__ unsigned hex2(unsigned x) {
    unsigned r; asm("ex2.approx.f16x2 %0, %1;" : "=r"(r) : "r"(x)); return r;
}
__device__ __forceinline__ void mma16(float* d, const unsigned* a,
                                      unsigned b0, unsigned b1) {
    asm volatile(
        "mma.sync.aligned.m16n8k16.row.col.f32.f16.f16.f32 "
        "{%0,%1,%2,%3}, {%4,%5,%6,%7}, {%8,%9}, {%0,%1,%2,%3};"
        : "+f"(d[0]), "+f"(d[1]), "+f"(d[2]), "+f"(d[3])
        : "r"(a[0]), "r"(a[1]), "r"(a[2]), "r"(a[3]), "r"(b0), "r"(b1));
}
__device__ __forceinline__ void ldsm4(unsigned& r0, unsigned& r1,
                                      unsigned& r2, unsigned& r3, unsigned a) {
    asm volatile("ldmatrix.sync.aligned.m8n8.x4.shared.b16 {%0,%1,%2,%3}, [%4];"
        : "=r"(r0), "=r"(r1), "=r"(r2), "=r"(r3) : "r"(a));
}
__device__ __forceinline__ void ldsm4t(unsigned& r0, unsigned& r1,
                                       unsigned& r2, unsigned& r3, unsigned a) {
    asm volatile("ldmatrix.sync.aligned.m8n8.x4.trans.shared.b16 {%0,%1,%2,%3}, [%4];"
        : "=r"(r0), "=r"(r1), "=r"(r2), "=r"(r3) : "r"(a));
}
__device__ __forceinline__ void cpa16(unsigned dst, const void* src) {
    asm volatile("cp.async.ca.shared.global [%0], [%1], 16;"
        :: "r"(dst), "l"(src));
}
__device__ __forceinline__ void cpa_commit() {
    asm volatile("cp.async.commit_group;");
}
__device__ __forceinline__ void cpa_wait0() {
    asm volatile("cp.async.wait_group 0;" ::: "memory");
}
__device__ __forceinline__ void cpa_wait1() {
    asm volatile("cp.async.wait_group 1;" ::: "memory");
}

// ---------------------------------------------------------------------------
// f32 -> fp16 bulk convert (8 elems/thread)
// ---------------------------------------------------------------------------
__global__ __launch_bounds__(256)
void f2h(const float* __restrict__ in, __half* __restrict__ out, int n)
{
    int i = (blockIdx.x * 256 + threadIdx.x) * 8;
    if (i >= n) return;
    float4 a = *(const float4*)(in + i);
    float4 b = *(const float4*)(in + i + 4);
    *(uint4*)(out + i) = make_uint4(pack2(a.x, a.y), pack2(a.z, a.w),
                                    pack2(b.x, b.y), pack2(b.z, b.w));
}

// ---------------------------------------------------------------------------
// All-fp16 cp.async 3-stage pipelined GEMM: C[M,N] = A @ B^T + bias
// MODE 0: f32 write to C; MODE 1: qkv scatter to fp16 buffers (k * KSCALE)
// CTA 128x128, 256 threads (8 warps 4x2), warp 32x64, kc=32.
// Each thread copies 2x16B per matrix per stage (full 8192B tile).
// ---------------------------------------------------------------------------
#define GST 40                         // half stride (32 + pad 8)
#define GSOF (128*GST*2)               // bytes per stage per matrix
#define GEMM_SMEM (2*3*128*GST*2)      // 61.4 KB

template<int MODE>
__global__ __launch_bounds__(256, 2)
void gemm_hh(const __half* __restrict__ A, const __half* __restrict__ B,
             const float* __restrict__ bias, float* __restrict__ C,
             int M, int N, int K,
             __half* __restrict__ qo, __half* __restrict__ ko,
             __half* __restrict__ vo)
{
    extern __shared__ __half gsm[];
    __half* As = gsm;                  // [3][128][GST]
    __half* Bs = gsm + 3 * 128 * GST;

    const int tid = threadIdx.x;
    const int wid = tid >> 5, lane = tid & 31;
    const int lg = lane >> 2, la3 = lane & 3;
    const int wm = wid & 3, wn = wid >> 2;
    const int bm = blockIdx.y * 128, bn = blockIdx.x * 128;

    float acc[2][8][4];
    #pragma unroll
    for (int mt = 0; mt < 2; mt++)
        #pragma unroll
        for (int nt = 0; nt < 8; nt++)
            #pragma unroll
            for (int i = 0; i < 4; i++) acc[mt][nt][i] = 0.f;

    const int lrow = tid >> 1, lcolh = (tid & 1) * 16;  // 128 rows x 32 halfs
    const __half* Ap = A + (size_t)(bm + lrow) * K + lcolh;
    const __half* Bp = B + (size_t)(bn + lrow) * K + lcolh;
    const unsigned adst = su32(As + lrow * GST + lcolh);
    const unsigned bdst = su32(Bs + lrow * GST + lcolh);

    // prologue: stages 0 and 1 (2 x 16B per matrix per thread)
    cpa16(adst,      Ap);      cpa16(adst + 16,       Ap + 8);
    cpa16(bdst,      Bp);      cpa16(bdst + 16,       Bp + 8);
    cpa_commit();
    cpa16(adst+GSOF, Ap + 32); cpa16(adst + GSOF + 16, Ap + 40);
    cpa16(bdst+GSOF, Bp + 32); cpa16(bdst + GSOF + 16, Bp + 40);
    cpa_commit();

    const unsigned a_frag = su32(As + (wm * 32 + (lane & 15)) * GST + (lane >> 4) * 8);
    const unsigned b_frag = su32(Bs + (wn * 64 + ((lane & 7) + ((lane >> 4) << 3))) * GST)
                            + (lane & 8) * 2;

    const int NIT = K / 32;
    int s = 0;
    for (int it = 0; it < NIT; it++) {
        cpa_wait1();
        __syncthreads();
        const unsigned soff = s * GSOF;

        #pragma unroll
        for (int ks = 0; ks < 2; ks++) {
            unsigned af[2][4];
            #pragma unroll
            for (int mt = 0; mt < 2; mt++)
                ldsm4(af[mt][0], af[mt][1], af[mt][2], af[mt][3],
                      a_frag + soff + (mt * 16 * GST + ks * 16) * 2);
            #pragma unroll
            for (int n16 = 0; n16 < 4; n16++) {
                unsigned r0, r1, r2, r3;
                ldsm4(r0, r1, r2, r3,
                      b_frag + soff + (n16 * 16 * GST + ks * 16) * 2);
                #pragma unroll
                for (int mt = 0; mt < 2; mt++) {
                    mma16(acc[mt][2 * n16    ], af[mt], r0, r1);
                    mma16(acc[mt][2 * n16 + 1], af[mt], r2, r3);
                }
            }
        }

        if (it + 2 < NIT) {       // stream stage it+2 into slot (it+2)%3
            int ns = s + 2; if (ns >= 3) ns -= 3;
            const int k0 = 32 * (it + 2);
            cpa16(adst + ns * GSOF,      Ap + k0);
            cpa16(adst + ns * GSOF + 16, Ap + k0 + 8);
            cpa16(bdst + ns * GSOF,      Bp + k0);
            cpa16(bdst + ns * GSOF + 16, Bp + k0 + 8);
        }
        cpa_commit();
        if (++s == 3) s = 0;
    }

    #pragma unroll
    for (int mt = 0; mt < 2; mt++)
        #pragma unroll
        for (int nt = 0; nt < 8; nt++) {
            const int row0 = bm + wm * 32 + mt * 16 + lg;
            const int col  = bn + wn * 64 + nt * 8 + 2 * la3;
            float v0 = acc[mt][nt][0] + bias[col];
            float v1 = acc[mt][nt][1] + bias[col + 1];
            float v2 = acc[mt][nt][2] + bias[col];
            float v3 = acc[mt][nt][3] + bias[col + 1];
            if (MODE == 0) {
                *(float2*)&C[(size_t)row0 * N + col]       = make_float2(v0, v1);
                *(float2*)&C[(size_t)(row0 + 8) * N + col] = make_float2(v2, v3);
            } else {
                const int g = col >> 10, rem = col & 1023;
                if (g == 1) { v0 *= KSCALE; v1 *= KSCALE; v2 *= KSCALE; v3 *= KSCALE; }
                __half* dst = (g == 0) ? qo : (g == 1) ? ko : vo;
                *(unsigned*)&dst[(size_t)row0 * DM + rem]       = pack2(v0, v1);
                *(unsigned*)&dst[(size_t)(row0 + 8) * DM + rem] = pack2(v2, v3);
            }
        }
}

// ---------------------------------------------------------------------------
// FP16 tensor-core causal flash attention (unchanged, passed round 7).
// CTA: 256 threads (8 warps), Q tile 128 rows (16/warp), kv tile 64.
// exp2-domain softmax with f16x2 MUFU; row sums via ones-MMA; cp.async
// double-buffered K/V. smem 54KB dynamic -> 2 CTAs/SM.
// ---------------------------------------------------------------------------
#define AST 72
#define ATTN_SMEM ((128*AST + 4*64*AST) * 2)
#define ONES2 0x3C003C00u

__global__ __launch_bounds__(256, 2)
void attn_h(const __half* __restrict__ Qb, const __half* __restrict__ Kb,
            const __half* __restrict__ Vb, __half* __restrict__ Ob)
{
    extern __shared__ __half dsm[];
    __half* Qsm = dsm;                         // [128][AST]
    __half* Ksm = dsm + 128 * AST;             // [2][64][AST]
    __half* Vsm = dsm + 128 * AST + 2 * 64 * AST;

    const int qt = (int)gridDim.x - 1 - (int)blockIdx.x;   // long rows first
    const int h = blockIdx.y, b = blockIdx.z;
    const int tid = threadIdx.x, wid = tid >> 5, lane = tid & 31;
    const int lg = lane >> 2, la3 = lane & 3;
    const int wb = wid * 16;
    const float NEG_INF = __int_as_float(0xff800000);

    const size_t base = (size_t)b * SEQ * DM + (size_t)h * HD;
    const int sr = tid >> 3, sc = (tid & 7) * 8;
    const unsigned SOFF = 64 * AST * 2;

    {
        const __half* Kg = Kb + base;
        const __half* Vg = Vb + base;
        #pragma unroll
        for (int p = 0; p < 2; p++) {
            const int r = sr + p * 32;
            cpa16(su32(Ksm + r * AST + sc), Kg + (size_t)r * DM + sc);
            cpa16(su32(Vsm + r * AST + sc), Vg + (size_t)r * DM + sc);
        }
        cpa_commit();
    }

    {
        const __half* Qg = Qb + base + (size_t)(qt * 128) * DM;
        #pragma unroll
        for (int p = 0; p < 4; p++) {
            const int r = sr + p * 32;
            *(uint4*)(Qsm + r * AST + sc) = *(const uint4*)(Qg + (size_t)r * DM + sc);
        }
    }
    __syncthreads();
    unsigned Qf[4][4];
    {
        unsigned qaddr = su32(Qsm + (wb + (lane & 15)) * AST + (lane >> 4) * 8);
        #pragma unroll
        for (int k16 = 0; k16 < 4; k16++)
            ldsm4(Qf[k16][0], Qf[k16][1], Qf[k16][2], Qf[k16][3],
                  qaddr + k16 * 32);
    }

    const unsigned kbase = su32(Ksm) +
        ((lane & 7) + ((lane >> 4) << 3)) * (AST * 2) + (lane & 8) * 2;
    const unsigned vbase = su32(Vsm) +
        (lane & 15) * (AST * 2) + (lane >> 4) * 16;

    float m0 = NEG_INF, m1 = NEG_INF, l0 = 0.f, l1 = 0.f;
    float O[8][4];
    #pragma unroll
    for (int nt = 0; nt < 8; nt++)
        #pragma unroll
        for (int i = 0; i < 4; i++) O[nt][i] = 0.f;

    const int ntiles = 2 * qt + 2;
    for (int kt = 0; kt < ntiles; kt++) {
        const int cur = kt & 1;
        cpa_wait0();
        __syncthreads();

        if (kt + 1 < ntiles) {
            const __half* Kg = Kb + base + (size_t)((kt + 1) * 64) * DM;
            const __half* Vg = Vb + base + (size_t)((kt + 1) * 64) * DM;
            const int s = cur ^ 1;
            #pragma unroll
            for (int p = 0; p < 2; p++) {
                const int r = sr + p * 32;
                cpa16(su32(Ksm) + s * SOFF + (r * AST + sc) * 2,
                      Kg + (size_t)r * DM + sc);
                cpa16(su32(Vsm) + s * SOFF + (r * AST + sc) * 2,
                      Vg + (size_t)r * DM + sc);
            }
            cpa_commit();
        }

        const unsigned kaddr = kbase + cur * SOFF;
        const unsigned vaddr = vbase + cur * SOFF;

        float S[8][4];
        #pragma unroll
        for (int nt = 0; nt < 8; nt++)
            #pragma unroll
            for (int i = 0; i < 4; i++) S[nt][i] = 0.f;

        #pragma unroll
        for (int k16 = 0; k16 < 4; k16++)
            #pragma unroll
            for (int n16 = 0; n16 < 4; n16++) {
                unsigned r0, r1, r2, r3;
                ldsm4(r0, r1, r2, r3,
                      kaddr + n16 * 16 * (AST * 2) + k16 * 32);
                mma16(S[2 * n16    ], Qf[k16], r0, r1);
                mma16(S[2 * n16 + 1], Qf[k16], r2, r3);
            }

        if (kt >= 2 * qt) {
            const int rg0 = qt * 128 + wb + lg, rg1 = rg0 + 8;
            #pragma unroll
            for (int nt = 0; nt < 8; nt++) {
                const int cg = kt * 64 + nt * 8 + 2 * la3;
                if (cg     > rg0) S[nt][0] = NEG_INF;
                if (cg + 1 > rg0) S[nt][1] = NEG_INF;
                if (cg     > rg1) S[nt][2] = NEG_INF;
                if (cg + 1 > rg1) S[nt][3] = NEG_INF;
            }
        }

        float mx0 = NEG_INF, mx1 = NEG_INF;
        #pragma unroll
        for (int nt = 0; nt < 8; nt++) {
            mx0 = fmaxf(mx0, fmaxf(S[nt][0], S[nt][1]));
            mx1 = fmaxf(mx1, fmaxf(S[nt][2], S[nt][3]));
        }
        mx0 = fmaxf(mx0, __shfl_xor_sync(0xffffffffu, mx0, 1));
        mx0 = fmaxf(mx0, __shfl_xor_sync(0xffffffffu, mx0, 2));
        mx1 = fmaxf(mx1, __shfl_xor_sync(0xffffffffu, mx1, 1));
        mx1 = fmaxf(mx1, __shfl_xor_sync(0xffffffffu, mx1, 2));
        const float mn0 = fmaxf(m0, mx0), mn1 = fmaxf(m1, mx1);
        const float al0 = ex2f(m0 - mn0), al1 = ex2f(m1 - mn1);
        m0 = mn0;  m1 = mn1;

        unsigned Pf[4][4];
        #pragma unroll
        for (int k16 = 0; k16 < 4; k16++) {
            Pf[k16][0] = hex2(pack2(S[2*k16  ][0] - mn0, S[2*k16  ][1] - mn0));
            Pf[k16][1] = hex2(pack2(S[2*k16  ][2] - mn1, S[2*k16  ][3] - mn1));
            Pf[k16][2] = hex2(pack2(S[2*k16+1][0] - mn0, S[2*k16+1][1] - mn0));
            Pf[k16][3] = hex2(pack2(S[2*k16+1][2] - mn1, S[2*k16+1][3] - mn1));
        }

        float ssum[4] = {0.f, 0.f, 0.f, 0.f};
        #pragma unroll
        for (int k16 = 0; k16 < 4; k16++)
            mma16(ssum, Pf[k16], ONES2, ONES2);
        l0 = l0 * al0 + ssum[0];
        l1 = l1 * al1 + ssum[2];

        #pragma unroll
        for (int nt = 0; nt < 8; nt++) {
            O[nt][0] *= al0;  O[nt][1] *= al0;
            O[nt][2] *= al1;  O[nt][3] *= al1;
        }

        #pragma unroll
        for (int k16 = 0; k16 < 4; k16++)
            #pragma unroll
            for (int n16 = 0; n16 < 4; n16++) {
                unsigned r0, r1, r2, r3;
                ldsm4t(r0, r1, r2, r3,
                       vaddr + k16 * 16 * (AST * 2) + n16 * 32);
                mma16(O[2 * n16    ], Pf[k16], r0, r1);
                mma16(O[2 * n16 + 1], Pf[k16], r2, r3);
            }
    }

    __half* Og = Ob + base + (size_t)(qt * 128) * DM;
    const float il0 = 1.0f / l0, il1 = 1.0f / l1;
    const int r0 = wb + lg, r1 = r0 + 8;
    #pragma unroll
    for (int nt = 0; nt < 8; nt++) {
        const int col = nt * 8 + 2 * la3;
        *(unsigned*)&Og[(size_t)r0 * DM + col] =
            pack2(O[nt][0] * il0, O[nt][1] * il0);
        *(unsigned*)&Og[(size_t)r1 * DM + col] =
            pack2(O[nt][2] * il1, O[nt][3] * il1);
    }
}

// ---------------------------------------------------------------------------
extern "C" void kernel_launch(void* const* d_in, const int* in_sizes, int n_in,
                              void* d_out, int out_size)
{
    const float* x  = (const float*)d_in[0];
    const float* Ww = (const float*)d_in[1];
    const float* Wb = (const float*)d_in[2];
    const float* Ow = (const float*)d_in[3];
    const float* Ob = (const float*)d_in[4];
    float* out = (float*)d_out;

    __half *q, *k, *v, *c1, *c2, *xh, *wh, *oh;
    cudaGetSymbolAddress((void**)&q,  g_q);
    cudaGetSymbolAddress((void**)&k,  g_k);
    cudaGetSymbolAddress((void**)&v,  g_v);
    cudaGetSymbolAddress((void**)&c1, g_c1);
    cudaGetSymbolAddress((void**)&c2, g_c2);
    cudaGetSymbolAddress((void**)&xh, g_xh);
    cudaGetSymbolAddress((void**)&wh, g_wh);
    cudaGetSymbolAddress((void**)&oh, g_oh);

    cudaFuncSetAttribute(attn_h,
                         cudaFuncAttributeMaxDynamicSharedMemorySize, ATTN_SMEM);
    cudaFuncSetAttribute(gemm_hh<0>,
                         cudaFuncAttributeMaxDynamicSharedMemorySize, GEMM_SMEM);
    cudaFuncSetAttribute(gemm_hh<1>,
                         cudaFuncAttributeMaxDynamicSharedMemorySize, GEMM_SMEM);

    // 0) one-time fp16 conversions
    f2h<<<(MROWS * DM) / 2048, 256>>>(x,  xh, MROWS * DM);
    f2h<<<(3 * DM * DM) / 2048, 256>>>(Ww, wh, 3 * DM * DM);
    f2h<<<(DM * DM) / 2048, 256>>>(Ow, oh, DM * DM);

    // 1) QKV projection + bias -> fp16 q/k/v (k pre-scaled by log2e/8)
    dim3 g1(3 * DM / 128, MROWS / 128);
    gemm_hh<1><<<g1, 256, GEMM_SMEM>>>(xh, wh, Wb, nullptr,
                                       MROWS, 3 * DM, DM, q, k, v);

    // 2-4) repeated causal attention (fp16 in/out)
    dim3 ga(SEQ / 128, NH, BATCH);
    attn_h<<<ga, 256, ATTN_SMEM>>>(q,  k, v, c1);
    attn_h<<<ga, 256, ATTN_SMEM>>>(c1, k, v, c2);
    attn_h<<<ga, 256, ATTN_SMEM>>>(c2, k, v, c1);

    // 5) output projection + bias (f32 out)
    dim3 g2(DM / 128, MROWS / 128);
    gemm_hh<0><<<g2, 256, GEMM_SMEM>>>(c1, oh, Ob, out, MROWS, DM, DM,
                                       nullptr, nullptr, nullptr);
}